// round 17
// baseline (speedup 1.0000x reference)
#include <cuda_runtime.h>
#include <cuda_bf16.h>
#include <math.h>
#include <stdint.h>
#include <string.h>

// ---------------------------------------------------------------------------
// LSTM autoencoder: persistent kernel, bf16 split-precision tensor-core GEMM
// (mma.sync.m16n8k16 fp32-accum, AhBh + AhBl + AlBh), decoupled layer sync.
// 256 threads/CTA, 8 warps: warps 0-3 cover z-cols [0,16), warps 4-7 cover
// [16,32) (N-split). Tile per CTA: 64 batch rows x 32 z-cols. 232 CTAs.
// Layers (I,H): L0(256,512) L1(512,256) L2(256,64) L3(64,256) L4(256,512)
//               L5(512,256).  B=64, T=256.
// ---------------------------------------------------------------------------

#define BATCH 64
#define TSTEPS 256
#define NCTA 232
#define NTHR 256
#define SMEM_BYTES 61952

// Sequence buffers as bf16 hi/lo pairs, time-major [T][B][H]
__device__ __nv_bfloat16 g_s0h[TSTEPS * BATCH * 512], g_s0l[TSTEPS * BATCH * 512];
__device__ __nv_bfloat16 g_s1h[TSTEPS * BATCH * 256], g_s1l[TSTEPS * BATCH * 256];
__device__ __nv_bfloat16 g_s2h[TSTEPS * BATCH * 64],  g_s2l[TSTEPS * BATCH * 64];
__device__ __nv_bfloat16 g_s3h[TSTEPS * BATCH * 256], g_s3l[TSTEPS * BATCH * 256];
__device__ __nv_bfloat16 g_s4h[TSTEPS * BATCH * 512], g_s4l[TSTEPS * BATCH * 512];
__device__ __nv_bfloat16 g_s5h[TSTEPS * BATCH * 256], g_s5l[TSTEPS * BATCH * 256];
__device__ __nv_bfloat16 g_xh[TSTEPS * BATCH * 256],  g_xl[TSTEPS * BATCH * 256];
__device__ float g_cell[6 * BATCH * 512];
// Packed weights: per layer, per tile g (8 h-cols = 32 z-cols), per k64 chunk:
// 2048 u32 words = [c4(4)][nt(4)][half(2)][lane(32)][j(2)]; each word a bf16
// pair (k0, k0+1) matching the m16n8k16 B fragment. nt == gate.
__device__ __align__(256) unsigned g_packed[5128192];
// Per-layer completion counters (monotonic within a replay).
__device__ unsigned g_done[8];

#define OFF0 0
#define OFF1 1572864
#define OFF2 2359296
#define OFF3 2441216
#define OFF4 2768896
#define OFF5 4341760

// ---------------------------------------------------------------------------
__global__ void init_counters() {
    if (threadIdx.x < 8) g_done[threadIdx.x] = 0;
}

__device__ __forceinline__ unsigned short bits_of(__nv_bfloat16 v) {
    unsigned short s;
    memcpy(&s, &v, 2);
    return s;
}

// Repack one element of W [I,4H] / U [H,4H] into the bf16 hi/lo B-fragment
// layout (32-col tiles). w indexes 4H*K words.
template <int I, int H>
__device__ __forceinline__ void repack_one(int w, const float* __restrict__ W,
                                           const float* __restrict__ U,
                                           unsigned* __restrict__ out) {
    constexpr int K = I + H;
    constexpr int N4 = 4 * H;
    int r2 = w & 2047;
    int rest = w >> 11;
    int chunk = rest % (K >> 6);
    int g = rest / (K >> 6);
    int c4 = r2 >> 9;
    int nt = (r2 >> 7) & 3;  // = gate
    int half = (r2 >> 6) & 1;
    int lane = (r2 >> 1) & 31;
    int j = r2 & 1;
    int k0 = (chunk * 4 + c4) * 16 + (lane & 3) * 2 + j * 8;
    int hcol = g * 8 + (lane >> 2);
    int col = nt * H + hcol;
    float v0 = (k0 < I) ? W[k0 * N4 + col] : U[(k0 - I) * N4 + col];
    float v1 = (k0 + 1 < I) ? W[(k0 + 1) * N4 + col]
                            : U[(k0 + 1 - I) * N4 + col];
    __nv_bfloat16 h0 = __float2bfloat16(v0);
    __nv_bfloat16 h1 = __float2bfloat16(v1);
    unsigned short u0, u1;
    if (half == 0) {
        u0 = bits_of(h0);
        u1 = bits_of(h1);
    } else {
        u0 = bits_of(__float2bfloat16(v0 - __bfloat162float(h0)));
        u1 = bits_of(__float2bfloat16(v1 - __bfloat162float(h1)));
    }
    out[((size_t)g * (K >> 6) + chunk) * 2048 + r2] =
        (unsigned)u0 | ((unsigned)u1 << 16);
}

template <int I1, int H1, int I2, int H2>
__global__ void repack2(const float* W1, const float* U1, unsigned* o1,
                        const float* W2, const float* U2, unsigned* o2) {
    const int t1 = 4 * H1 * (I1 + H1);
    const int t2 = 4 * H2 * (I2 + H2);
    for (int w = blockIdx.x * blockDim.x + threadIdx.x; w < t1 + t2;
         w += gridDim.x * blockDim.x) {
        if (w < t1) repack_one<I1, H1>(w, W1, U1, o1);
        else        repack_one<I2, H2>(w - t1, W2, U2, o2);
    }
}

// Split x [B][T][256] into time-major bf16 hi/lo [T][B][256].
__global__ void split_x(const float* __restrict__ x) {
    const int total = TSTEPS * BATCH * 256;
    for (int i = blockIdx.x * blockDim.x + threadIdx.x; i < total;
         i += gridDim.x * blockDim.x) {
        int t = i >> 14;
        int rem = i & 16383;
        int row = rem >> 8;
        int k = rem & 255;
        float v = x[row * 65536 + t * 256 + k];
        __nv_bfloat16 h = __float2bfloat16(v);
        g_xh[i] = h;
        g_xl[i] = __float2bfloat16(v - __bfloat162float(h));
    }
}

// ---------------------------------------------------------------------------
__device__ __forceinline__ void cp16(uint32_t saddr, const void* gaddr) {
    asm volatile("cp.async.cg.shared.global [%0], [%1], 16;"
                 :: "r"(saddr), "l"(gaddr) : "memory");
}
__device__ __forceinline__ void cp_commit() {
    asm volatile("cp.async.commit_group;" ::: "memory");
}
__device__ __forceinline__ void cp_wait1() {
    asm volatile("cp.async.wait_group 1;" ::: "memory");
}
__device__ __forceinline__ void ldsm4(uint32_t& r0, uint32_t& r1, uint32_t& r2,
                                      uint32_t& r3, uint32_t addr) {
    asm volatile("ldmatrix.sync.aligned.m8n8.x4.shared.b16 {%0,%1,%2,%3}, [%4];"
                 : "=r"(r0), "=r"(r1), "=r"(r2), "=r"(r3) : "r"(addr));
}
__device__ __forceinline__ void lds2(uint32_t& r0, uint32_t& r1, uint32_t addr) {
    asm volatile("ld.shared.v2.b32 {%0,%1}, [%2];"
                 : "=r"(r0), "=r"(r1) : "r"(addr));
}
__device__ __forceinline__ void hmma(float* d, uint32_t a0, uint32_t a1,
                                     uint32_t a2, uint32_t a3, uint32_t b0,
                                     uint32_t b1) {
    asm volatile(
        "mma.sync.aligned.m16n8k16.row.col.f32.bf16.bf16.f32 "
        "{%0,%1,%2,%3}, {%4,%5,%6,%7}, {%8,%9}, {%0,%1,%2,%3};"
        : "+f"(d[0]), "+f"(d[1]), "+f"(d[2]), "+f"(d[3])
        : "r"(a0), "r"(a1), "r"(a2), "r"(a3), "r"(b0), "r"(b1));
}
__device__ __forceinline__ void spin_until(unsigned* cnt, unsigned target) {
    unsigned v;
    do {
        asm volatile("ld.acquire.gpu.global.u32 %0, [%1];"
                     : "=r"(v) : "l"(cnt) : "memory");
    } while (v < target);
}
__device__ __forceinline__ void arrive(unsigned* cnt) {
    asm volatile("red.release.gpu.global.add.u32 [%0], 1;"
                 :: "l"(cnt) : "memory");
}

// ---------------------------------------------------------------------------
// Shared arena layout (61952 B):
//   A: stage(2) x half(2) x [64 rows x 144 B] = 36864          (off 0)
//   B: stage(2) x 8192                        = 16384          (off 36864)
//   Z: 64 x 34 fp32                           =  8704          (off 53248)
// ---------------------------------------------------------------------------
template <int I, int H, bool TANH, bool OUT>
__device__ __forceinline__ void layer_step(
    int g, int t,
    const __nv_bfloat16* __restrict__ xinh,
    const __nv_bfloat16* __restrict__ xinl,
    __nv_bfloat16* __restrict__ hqh, __nv_bfloat16* __restrict__ hql,
    float* __restrict__ cbuf, const unsigned* __restrict__ Bp,
    const float* __restrict__ bias, float* __restrict__ outp,
    unsigned char* arena,
    unsigned* ownCnt, unsigned ownN, unsigned* prodCnt, unsigned prodN) {
    constexpr int K = I + H;
    constexpr int HCHUNK = I >> 6;  // first h chunk index
    static_assert((I & 63) == 0 && (K & 63) == 0, "chunking");
    const int tid = threadIdx.x, lane = tid & 31, warp = tid >> 5;
    const int mwarp = warp & 3;   // m16 row group
    const int nhalf = warp >> 2;  // z-col half: nt in {nhalf*2, nhalf*2+1}
    const uint32_t sbase = (uint32_t)__cvta_generic_to_shared(arena);
    const int nch = ((t == 0) ? I : K) >> 6;
    const unsigned* BpG = Bp + (size_t)g * ((K >> 6) << 11);
    const __nv_bfloat16* hh = hqh + (size_t)(t - 1) * BATCH * H;
    const __nv_bfloat16* hl = hql + (size_t)(t - 1) * BATCH * H;
    const __nv_bfloat16* xh = xinh + (size_t)t * BATCH * I;
    const __nv_bfloat16* xl = xinl + (size_t)t * BATCH * I;

    // Wait for this timestep's input from the producer layer.
    if (prodCnt) {
        if (tid == 0) spin_until(prodCnt, (unsigned)(t + 1) * prodN);
        __syncthreads();
    }

    auto issue = [&](int c) {
        if (c < nch) {
            const int kc = c << 6;
            const __nv_bfloat16 *sh, *sl;
            int dim, off;
            if (kc < I) { sh = xh; sl = xl; dim = I; off = kc; }
            else        { sh = hh; sl = hl; dim = H; off = kc - I; }
            uint32_t ab = sbase + (uint32_t)((c & 1) * 18432);
#pragma unroll
            for (int i = 0; i < 2; ++i) {
                int q = tid + i * NTHR;
                int row = q >> 3, unit = q & 7;
                cp16(ab + row * 144 + unit * 16,
                     sh + (size_t)row * dim + off + unit * 8);
            }
#pragma unroll
            for (int i = 0; i < 2; ++i) {
                int q = tid + i * NTHR;
                int row = q >> 3, unit = q & 7;
                cp16(ab + 9216 + row * 144 + unit * 16,
                     sl + (size_t)row * dim + off + unit * 8);
            }
            uint32_t bb = sbase + 36864u + (uint32_t)((c & 1) * 8192);
#pragma unroll
            for (int i = 0; i < 2; ++i) {
                int q = tid + i * NTHR;
                cp16(bb + q * 16, BpG + (size_t)c * 2048 + q * 4);
            }
        }
        cp_commit();
    };

    // Before issuing the first h-chunk, wait for own layer's step t-1.
    auto wait_h = [&](int j) {
        if (j == HCHUNK && t > 0) {
            if (tid == 0) spin_until(ownCnt, (unsigned)t * ownN);
            __syncthreads();
        }
    };

    float d[2][4];
#pragma unroll
    for (int jn = 0; jn < 2; ++jn)
#pragma unroll
        for (int e = 0; e < 4; ++e) d[jn][e] = 0.f;

    const int sel = lane >> 3, rowin = lane & 7;
    const uint32_t aRow =
        (uint32_t)((mwarp * 16 + (sel & 1) * 8 + rowin) * 144 +
                   (sel >> 1) * 16);

    wait_h(0);
    issue(0);
    wait_h(1);
    issue(1);

    for (int c = 0; c < nch; ++c) {
        cp_wait1();
        __syncthreads();
        uint32_t aH = sbase + (uint32_t)((c & 1) * 18432) + aRow;
        uint32_t aL = aH + 9216;
        uint32_t bB = sbase + 36864u + (uint32_t)((c & 1) * 8192) + lane * 8 +
                      (uint32_t)(nhalf * 1024);  // nt base = nhalf*2
#pragma unroll
        for (int c4 = 0; c4 < 4; ++c4) {
            uint32_t ah0, ah1, ah2, ah3, al0, al1, al2, al3;
            ldsm4(ah0, ah1, ah2, ah3, aH + c4 * 32);
            ldsm4(al0, al1, al2, al3, aL + c4 * 32);
            uint32_t bo = bB + (uint32_t)(c4 * 2048);
#pragma unroll
            for (int jn = 0; jn < 2; ++jn) {
                uint32_t bh0, bh1, bl0, bl1;
                lds2(bh0, bh1, bo + jn * 512);
                lds2(bl0, bl1, bo + jn * 512 + 256);
                hmma(d[jn], ah0, ah1, ah2, ah3, bh0, bh1);
                hmma(d[jn], ah0, ah1, ah2, ah3, bl0, bl1);
                hmma(d[jn], al0, al1, al2, al3, bh0, bh1);
            }
        }
        __syncthreads();
        wait_h(c + 2);
        issue(c + 2);
    }

    // Epilogue: stage z into sZ[row][zcol] (pitch 34), zcol = gate*8 + hc.
    float* sZ = reinterpret_cast<float*>(arena + 53248);
    {
        int r0 = mwarp * 16 + (lane >> 2);
        int c0 = (lane & 3) * 2;
#pragma unroll
        for (int jn = 0; jn < 2; ++jn) {
            int nt = nhalf * 2 + jn;
            *reinterpret_cast<float2*>(&sZ[r0 * 34 + nt * 8 + c0]) =
                make_float2(d[jn][0], d[jn][1]);
            *reinterpret_cast<float2*>(&sZ[(r0 + 8) * 34 + nt * 8 + c0]) =
                make_float2(d[jn][2], d[jn][3]);
        }
    }
    __syncthreads();

    // Gate phase: thread -> (row = tid>>2, two h-cols).
    {
        const int row = tid >> 2;
        const int hcb = (tid & 3) * 2;
#pragma unroll
        for (int u = 0; u < 2; ++u) {
            const int hc = hcb + u;
            const int hcol = g * 8 + hc;
            float zi = sZ[row * 34 + hc] + bias[hcol];
            float zf = sZ[row * 34 + 8 + hc] + bias[H + hcol];
            float zg = sZ[row * 34 + 16 + hc] + bias[2 * H + hcol];
            float zo = sZ[row * 34 + 24 + hc] + bias[3 * H + hcol];
            float ig = 1.f / (1.f + expf(-zi));
            float fg = 1.f / (1.f + expf(-zf));
            float gg = TANH ? tanhf(zg) : fmaxf(zg, 0.f);
            float og = 1.f / (1.f + expf(-zo));
            float cp_ = (t == 0) ? 0.f : cbuf[row * H + hcol];
            float cn = fg * cp_ + ig * gg;
            cbuf[row * H + hcol] = cn;
            float hn = og * (TANH ? tanhf(cn) : fmaxf(cn, 0.f));
            size_t hidx = ((size_t)t * BATCH + row) * H + hcol;
            __nv_bfloat16 hb = __float2bfloat16(hn);
            hqh[hidx] = hb;
            hql[hidx] = __float2bfloat16(hn - __bfloat162float(hb));
            if (OUT && t == TSTEPS - 1) outp[row * H + hcol] = hn;
        }
    }
    __syncthreads();               // all writes done block-wide
    if (tid == 0) arrive(ownCnt);  // publish step t completion
}

// ---------------------------------------------------------------------------
// Persistent kernel, 232 CTAs, each loops over its OWN t:
// [0,64) L0 | [64,96) L1 | [96,160) L4 | [160,192) L5 | [192,224) L3 |
// [224,232) L2.
// ---------------------------------------------------------------------------
__global__ __launch_bounds__(NTHR, 2) void fused_kernel(
    const float* __restrict__ b0, const float* __restrict__ b1,
    const float* __restrict__ b2, const float* __restrict__ b3,
    const float* __restrict__ b4, const float* __restrict__ b5,
    float* __restrict__ outp) {
    extern __shared__ __align__(16) unsigned char sArena[];

    const int bid = blockIdx.x;

    if (bid < 64) {
        for (int t = 0; t < TSTEPS; ++t)
            layer_step<256, 512, false, false>(
                bid, t, g_xh, g_xl, g_s0h, g_s0l, g_cell + 0 * BATCH * 512,
                g_packed + OFF0, b0, nullptr, sArena, g_done + 0, 64, nullptr,
                0);
    } else if (bid < 96) {
        for (int t = 0; t < TSTEPS; ++t)
            layer_step<512, 256, false, false>(
                bid - 64, t, g_s0h, g_s0l, g_s1h, g_s1l,
                g_cell + 1 * BATCH * 512, g_packed + OFF1, b1, nullptr, sArena,
                g_done + 1, 32, g_done + 0, 64);
    } else if (bid < 160) {
        for (int t = 0; t < TSTEPS; ++t)
            layer_step<256, 512, false, false>(
                bid - 96, t, g_s3h, g_s3l, g_s4h, g_s4l,
                g_cell + 4 * BATCH * 512, g_packed + OFF4, b4, nullptr, sArena,
                g_done + 4, 64, g_done + 3, 32);
    } else if (bid < 192) {
        for (int t = 0; t < TSTEPS; ++t)
            layer_step<512, 256, true, true>(
                bid - 160, t, g_s4h, g_s4l, g_s5h, g_s5l,
                g_cell + 5 * BATCH * 512, g_packed + OFF5, b5, outp, sArena,
                g_done + 5, 32, g_done + 4, 64);
    } else if (bid < 224) {
        for (int t = 0; t < TSTEPS; ++t)
            layer_step<64, 256, false, false>(
                bid - 192, t, g_s2h, g_s2l, g_s3h, g_s3l,
                g_cell + 3 * BATCH * 512, g_packed + OFF3, b3, nullptr, sArena,
                g_done + 3, 32, g_done + 2, 8);
    } else {
        for (int t = 0; t < TSTEPS; ++t)
            layer_step<256, 64, false, false>(
                bid - 224, t, g_s1h, g_s1l, g_s2h, g_s2l,
                g_cell + 2 * BATCH * 512, g_packed + OFF2, b2, nullptr, sArena,
                g_done + 2, 8, g_done + 1, 32);
    }
}

// ---------------------------------------------------------------------------
extern "C" void kernel_launch(void* const* d_in, const int* in_sizes, int n_in,
                              void* d_out, int out_size) {
    (void)in_sizes; (void)n_in; (void)out_size;

    const float* x = (const float*)d_in[0];
    const float* W[6];
    const float* U[6];
    const float* b[6];
    for (int l = 0; l < 6; ++l) {
        W[l] = (const float*)d_in[1 + 3 * l];
        U[l] = (const float*)d_in[2 + 3 * l];
        b[l] = (const float*)d_in[3 + 3 * l];
    }

    unsigned* pk;
    cudaGetSymbolAddress((void**)&pk, g_packed);

    cudaFuncSetAttribute(fused_kernel,
                         cudaFuncAttributeMaxDynamicSharedMemorySize,
                         SMEM_BYTES);

    // 6 launches total; ncu -s 5 -c 1 lands on fused_kernel.
    init_counters<<<1, 32>>>();
    split_x<<<512, 256>>>(x);
    repack2<256, 512, 512, 256><<<512, 256>>>(W[0], U[0], pk + OFF0,
                                              W[1], U[1], pk + OFF1);
    repack2<256, 64, 64, 256><<<256, 256>>>(W[2], U[2], pk + OFF2,
                                            W[3], U[3], pk + OFF3);
    repack2<256, 512, 512, 256><<<512, 256>>>(W[4], U[4], pk + OFF4,
                                              W[5], U[5], pk + OFF5);

    fused_kernel<<<NCTA, NTHR, SMEM_BYTES>>>(b[0], b[1], b[2], b[3], b[4],
                                             b[5], (float*)d_out);
}